// round 4
// baseline (speedup 1.0000x reference)
#include <cuda_runtime.h>
#include <cuda_bf16.h>
#include <math.h>

// Problem constants (fixed shapes: x [8,512,64,64] fp32, mask [64,64] bool)
#define B 8
#define C 512
#define D 256              // C/2
#define N 4096             // 64*64
#define OUTC 768           // 3*D

// ---- device scratch (no allocation allowed) ----
__device__ float g_invnorm[B * N];
__device__ int   g_kidx[N];     // known (unmasked) pixel indices, ascending
__device__ int   g_qidx[N];     // hole (masked) pixel indices, ascending
__device__ int   g_counts[2];   // [0]=nKnown, [1]=nHole

// ============================================================
// K0: copy former+latter into out channels [0,512) and zero the
//     shift region [512,768). float4 vectorized.
//     out has 8*768*4096 floats = 6291456 float4.
// ============================================================
__global__ void k_copy_expand(const float4* __restrict__ x4, float4* __restrict__ o4) {
    int i = blockIdx.x * 256 + threadIdx.x;           // < 6291456
    int b = i / (OUTC * N / 4);                       // / 786432
    int r = i - b * (OUTC * N / 4);
    float4 v;
    if (r < C * N / 4) v = x4[b * (C * N / 4) + r];
    else               v = make_float4(0.f, 0.f, 0.f, 0.f);
    o4[i] = v;
}

// ============================================================
// K1: inv-norm of latter per (b, n):  1/(||latter[b,:,n]|| + 1e-8)
// ============================================================
__global__ void k_invnorm(const float* __restrict__ x) {
    int b = blockIdx.y;
    int n = blockIdx.x * 128 + threadIdx.x;
    const float* p = x + ((size_t)b * C + D) * N + n;
    float s = 0.f;
#pragma unroll 8
    for (int d = 0; d < D; ++d) {
        float v = p[(size_t)d * N];
        s = fmaf(v, v, s);
    }
    g_invnorm[b * N + n] = 1.0f / (sqrtf(s) + 1e-8f);
}

// ============================================================
// K2: build compact index lists from the mask, deterministically
//     (single block, Hillis-Steele scan). Robust mask decode:
//     - If any 32-bit word in the first safe 4KB is NOT in
//       {0, 1, 0x3F800000}, the mask is byte-packed (bool/uint8):
//       read bytes.
//     - Otherwise it is word-sized (int32 or float32): nonzero
//       bit pattern == True for both.
// ============================================================
__global__ void k_build_lists(const unsigned char* __restrict__ mask8) {
    __shared__ int cK[256], cH[256];
    __shared__ int byteEvidence;
    const int t = threadIdx.x;
    if (t == 0) byteEvidence = 0;
    __syncthreads();

    const unsigned int* m32 = (const unsigned int*)mask8;
    // first 1024 words == first 4096 bytes: safe for every candidate dtype
    int bad = 0;
    for (int w = t; w < 1024; w += 256) {
        unsigned int v = m32[w];
        if (v != 0u && v != 1u && v != 0x3F800000u) bad = 1;
    }
    if (bad) byteEvidence = 1;   // benign race, same value
    __syncthreads();
    const bool byteMode = (byteEvidence != 0);

    const int base = t * 16;     // 256 threads * 16 = 4096
    int ck = 0, ch = 0;
#pragma unroll
    for (int e = 0; e < 16; ++e) {
        int m = base + e;
        bool f = byteMode ? (mask8[m] != 0) : (m32[m] != 0u);
        if (f) ch++; else ck++;
    }
    cK[t] = ck; cH[t] = ch;
    __syncthreads();
    // inclusive scan over 256 entries
    for (int off = 1; off < 256; off <<= 1) {
        int a = (t >= off) ? cK[t - off] : 0;
        int b2 = (t >= off) ? cH[t - off] : 0;
        __syncthreads();
        cK[t] += a; cH[t] += b2;
        __syncthreads();
    }
    int kb = cK[t] - ck;   // exclusive prefixes
    int hb = cH[t] - ch;
#pragma unroll
    for (int e = 0; e < 16; ++e) {
        int m = base + e;
        bool f = byteMode ? (mask8[m] != 0) : (m32[m] != 0u);
        if (f) g_qidx[hb++] = m; else g_kidx[kb++] = m;
    }
    if (t == 255) { g_counts[0] = cK[255]; g_counts[1] = cH[255]; }
}

// ============================================================
// K3: flash-attention over hole queries.
//   CTA = (qtile of 64 hole queries, batch). 256 threads.
//   smem: Qs[256][64], Ks[256][64], Vs[64][272] (d-pad 16),
//         Ps[64][68], + index/scale caches.
//   Thread (tx=t&15, ty=t>>4):
//     S phase: 4q x 4k micro-tile, float4 smem reads.
//     PV phase: accumulates O[4q][16d], d = c*64 + tx*4 + r.
// ============================================================
#define QS_F   0
#define KS_F   16384
#define VS_F   32768             // 64*272 = 17408
#define VS_STR 272
#define PS_F   50176             // 64*68 = 4352
#define PS_STR 68
#define SKN_F  54528
#define SKI_F  54592
#define SQN_F  54656
#define SQI_F  54720
#define SMEM_FLOATS 54784
#define SMEM_BYTES  (SMEM_FLOATS * 4)   // 219136 B

__global__ __launch_bounds__(256, 1)
void k_attn(const float* __restrict__ x, float* __restrict__ out) {
    extern __shared__ float sm[];
    float* Qs  = sm + QS_F;
    float* Ks  = sm + KS_F;
    float* Vs  = sm + VS_F;
    float* Ps  = sm + PS_F;
    int*   sKn = (int*)(sm + SKN_F);
    float* sKi = sm + SKI_F;
    int*   sQn = (int*)(sm + SQN_F);
    float* sQi = sm + SQI_F;

    const int t  = threadIdx.x;
    const int tx = t & 15;
    const int ty = t >> 4;
    const int b  = blockIdx.y;
    const int qt = blockIdx.x;

    const int nKnown = g_counts[0];
    const int nHole  = g_counts[1];
    const int q0 = qt * 64;
    if (q0 >= nHole) return;
    const int nQ = min(64, nHole - q0);

    const float* lat = x + ((size_t)b * C + D) * N;  // latter
    const float* fmr = x + (size_t)b * C * N;        // former
    const float* inv = g_invnorm + b * N;

    if (t < 64) {
        int n = (t < nQ) ? g_qidx[q0 + t] : -1;
        sQn[t] = n;
        sQi[t] = (n >= 0) ? inv[n] : 0.f;
    }
    __syncthreads();

    // load Q tile (normalized latter at hole pixels), layout [d][q]
    for (int i = t; i < 64 * 256; i += 256) {
        int q = i & 63, d = i >> 6;
        int n = sQn[q];
        Qs[d * 64 + q] = (n >= 0) ? lat[(size_t)d * N + n] * sQi[q] : 0.f;
    }

    float Or[4][16];
#pragma unroll
    for (int i = 0; i < 4; ++i)
#pragma unroll
        for (int c = 0; c < 16; ++c) Or[i][c] = 0.f;
    float mi[4] = {-3e38f, -3e38f, -3e38f, -3e38f};
    float li[4] = {0.f, 0.f, 0.f, 0.f};

    const int nkt = (nKnown + 63) >> 6;
    for (int kt = 0; kt < nkt; ++kt) {
        const int kn = min(64, nKnown - kt * 64);
        __syncthreads();   // prior PV done (and, first iter, Q tile visible)
        if (t < 64) {
            int m = (t < kn) ? g_kidx[kt * 64 + t] : -1;
            sKn[t] = m;
            sKi[t] = (m >= 0) ? inv[m] : 0.f;
        }
        __syncthreads();
        // load K (normalized latter) [d][64] and V (former) transposed [kj][272]
        for (int i = t; i < 64 * 256; i += 256) {
            int kj = i & 63, d = i >> 6;
            int m = sKn[kj];
            float kv = 0.f, vv = 0.f;
            if (m >= 0) {
                kv = lat[(size_t)d * N + m] * sKi[kj];
                vv = fmr[(size_t)d * N + m];
            }
            Ks[d * 64 + kj] = kv;
            Vs[kj * VS_STR + d] = vv;
        }
        __syncthreads();

        // ---- S = Q^T K, 4x4 micro-tile ----
        float acc[4][4];
#pragma unroll
        for (int i = 0; i < 4; ++i)
#pragma unroll
            for (int j = 0; j < 4; ++j) acc[i][j] = 0.f;

        const float* qp = Qs + ty * 4;
        const float* kp = Ks + tx * 4;
#pragma unroll 4
        for (int d = 0; d < 256; ++d) {
            float4 qv = *(const float4*)qp; qp += 64;
            float4 kv = *(const float4*)kp; kp += 64;
            float qa[4] = {qv.x, qv.y, qv.z, qv.w};
            float ka[4] = {kv.x, kv.y, kv.z, kv.w};
#pragma unroll
            for (int i = 0; i < 4; ++i)
#pragma unroll
                for (int j = 0; j < 4; ++j)
                    acc[i][j] = fmaf(qa[i], ka[j], acc[i][j]);
        }

        // mask padded key columns (exp underflows to exactly 0)
#pragma unroll
        for (int j = 0; j < 4; ++j) {
            if (tx * 4 + j >= kn) {
#pragma unroll
                for (int i = 0; i < 4; ++i) acc[i][j] = -1e30f;
            }
        }

        // ---- online softmax per query row (16-lane groups) ----
#pragma unroll
        for (int i = 0; i < 4; ++i) {
            float tm = fmaxf(fmaxf(acc[i][0], acc[i][1]), fmaxf(acc[i][2], acc[i][3]));
#pragma unroll
            for (int o = 8; o; o >>= 1) tm = fmaxf(tm, __shfl_xor_sync(0xffffffffu, tm, o));
            float nm = fmaxf(mi[i], tm);
            float sc = __expf(mi[i] - nm);
            mi[i] = nm;
            float rs = 0.f;
#pragma unroll
            for (int j = 0; j < 4; ++j) {
                float p = __expf(acc[i][j] - nm);
                acc[i][j] = p;
                rs += p;
            }
#pragma unroll
            for (int o = 8; o; o >>= 1) rs += __shfl_xor_sync(0xffffffffu, rs, o);
            li[i] = li[i] * sc + rs;
#pragma unroll
            for (int c = 0; c < 16; ++c) Or[i][c] *= sc;
            *(float4*)&Ps[(ty * 4 + i) * PS_STR + tx * 4] =
                make_float4(acc[i][0], acc[i][1], acc[i][2], acc[i][3]);
        }
        __syncthreads();

        // ---- O += P * V^T ----
        const float* vp = Vs + tx * 4;
#pragma unroll 2
        for (int kj = 0; kj < 64; ++kj) {
            float va[16];
            *(float4*)&va[0]  = *(const float4*)(vp + kj * VS_STR);
            *(float4*)&va[4]  = *(const float4*)(vp + kj * VS_STR + 64);
            *(float4*)&va[8]  = *(const float4*)(vp + kj * VS_STR + 128);
            *(float4*)&va[12] = *(const float4*)(vp + kj * VS_STR + 192);
#pragma unroll
            for (int i = 0; i < 4; ++i) {
                float p = Ps[(ty * 4 + i) * PS_STR + kj];
#pragma unroll
                for (int c = 0; c < 16; ++c)
                    Or[i][c] = fmaf(p, va[c], Or[i][c]);
            }
        }
    }

    // ---- epilogue: normalize and scatter into shift channels ----
    float* ob = out + ((size_t)b * OUTC + 2 * D) * N;
#pragma unroll
    for (int i = 0; i < 4; ++i) {
        int qi = ty * 4 + i;
        if (qi < nQ) {
            int n = sQn[qi];
            float il = 1.0f / li[i];
#pragma unroll
            for (int c = 0; c < 4; ++c)
#pragma unroll
                for (int r = 0; r < 4; ++r) {
                    int d = c * 64 + tx * 4 + r;
                    ob[(size_t)d * N + n] = Or[i][c * 4 + r] * il;
                }
        }
    }
}

// ============================================================
extern "C" void kernel_launch(void* const* d_in, const int* in_sizes, int n_in,
                              void* d_out, int out_size) {
    const float* x = (const float*)d_in[0];
    const unsigned char* mask = (const unsigned char*)d_in[1];
    float* out = (float*)d_out;

    (void)in_sizes; (void)n_in; (void)out_size;

    // out copy + zero shift region: 6291456 float4 / 256 threads
    k_copy_expand<<<(B * OUTC * N / 4) / 256, 256>>>((const float4*)x, (float4*)out);
    k_invnorm<<<dim3(N / 128, B), 128>>>(x);
    k_build_lists<<<1, 256>>>(mask);

    cudaFuncSetAttribute(k_attn, cudaFuncAttributeMaxDynamicSharedMemorySize, SMEM_BYTES);
    // 64 qtiles covers up to 4096 hole queries; extra tiles early-exit
    k_attn<<<dim3(64, B), 256, SMEM_BYTES>>>(x, out);
}

// round 6
// speedup vs baseline: 8.0740x; 8.0740x over previous
#include <cuda_runtime.h>
#include <cuda_bf16.h>
#include <math.h>
#include <stdint.h>

// Problem constants (fixed shapes: x [8,512,64,64] fp32, mask [64,64] bool)
#define B 8
#define C 512
#define D 256              // C/2
#define N 4096             // 64*64
#define OUTC 768           // 3*D

// ---- device scratch (no allocation allowed) ----
__device__ float g_invnorm[B * N];
__device__ int   g_kidx[N];     // known (unmasked) pixel indices, ascending
__device__ int   g_qidx[N];     // hole (masked) pixel indices, ascending
__device__ int   g_counts[2];   // [0]=nKnown, [1]=nHole

// packed bf16 operands: [b][row][256] row-major, row = compact index
__device__ __align__(256) __nv_bfloat16 g_K[(size_t)B * 4096 * 256];
__device__ __align__(256) __nv_bfloat16 g_V[(size_t)B * 4096 * 256];
__device__ __align__(256) __nv_bfloat16 g_Q[(size_t)B * 4096 * 256];

// ============================================================
// PTX helpers
// ============================================================
__device__ __forceinline__ uint32_t smaddr(const void* p) {
    return (uint32_t)__cvta_generic_to_shared(p);
}
__device__ __forceinline__ void ldsm4(uint32_t* r, uint32_t a) {
    asm volatile("ldmatrix.sync.aligned.m8n8.x4.shared.b16 {%0,%1,%2,%3}, [%4];"
        : "=r"(r[0]), "=r"(r[1]), "=r"(r[2]), "=r"(r[3]) : "r"(a));
}
__device__ __forceinline__ void ldsm4t(uint32_t* r, uint32_t a) {
    asm volatile("ldmatrix.sync.aligned.m8n8.x4.trans.shared.b16 {%0,%1,%2,%3}, [%4];"
        : "=r"(r[0]), "=r"(r[1]), "=r"(r[2]), "=r"(r[3]) : "r"(a));
}
__device__ __forceinline__ void mma_bf16(float* c, const uint32_t* a, uint32_t b0, uint32_t b1) {
    asm volatile("mma.sync.aligned.m16n8k16.row.col.f32.bf16.bf16.f32 "
        "{%0,%1,%2,%3}, {%4,%5,%6,%7}, {%8,%9}, {%0,%1,%2,%3};"
        : "+f"(c[0]), "+f"(c[1]), "+f"(c[2]), "+f"(c[3])
        : "r"(a[0]), "r"(a[1]), "r"(a[2]), "r"(a[3]), "r"(b0), "r"(b1));
}
__device__ __forceinline__ void cpasync16(uint32_t s, const void* g) {
    asm volatile("cp.async.cg.shared.global [%0], [%1], 16;" :: "r"(s), "l"(g));
}

// ============================================================
// K0: copy former+latter into out channels [0,512), zero [512,768).
// ============================================================
__global__ void k_copy_expand(const float4* __restrict__ x4, float4* __restrict__ o4) {
    int i = blockIdx.x * 256 + threadIdx.x;           // < 6291456
    int b = i / (OUTC * N / 4);
    int r = i - b * (OUTC * N / 4);
    float4 v;
    if (r < C * N / 4) v = x4[b * (C * N / 4) + r];
    else               v = make_float4(0.f, 0.f, 0.f, 0.f);
    o4[i] = v;
}

// ============================================================
// K1: inv-norm of latter per (b, n)
// ============================================================
__global__ void k_invnorm(const float* __restrict__ x) {
    int b = blockIdx.y;
    int n = blockIdx.x * 128 + threadIdx.x;
    const float* p = x + ((size_t)b * C + D) * N + n;
    float s = 0.f;
#pragma unroll 8
    for (int d = 0; d < D; ++d) {
        float v = p[(size_t)d * N];
        s = fmaf(v, v, s);
    }
    g_invnorm[b * N + n] = 1.0f / (sqrtf(s) + 1e-8f);
}

// ============================================================
// K2: build compact index lists (unchanged, verified correct)
// ============================================================
__global__ void k_build_lists(const unsigned char* __restrict__ mask8) {
    __shared__ int cK[256], cH[256];
    __shared__ int byteEvidence;
    const int t = threadIdx.x;
    if (t == 0) byteEvidence = 0;
    __syncthreads();

    const unsigned int* m32 = (const unsigned int*)mask8;
    int bad = 0;
    for (int w = t; w < 1024; w += 256) {
        unsigned int v = m32[w];
        if (v != 0u && v != 1u && v != 0x3F800000u) bad = 1;
    }
    if (bad) byteEvidence = 1;
    __syncthreads();
    const bool byteMode = (byteEvidence != 0);

    const int base = t * 16;
    int ck = 0, ch = 0;
#pragma unroll
    for (int e = 0; e < 16; ++e) {
        int m = base + e;
        bool f = byteMode ? (mask8[m] != 0) : (m32[m] != 0u);
        if (f) ch++; else ck++;
    }
    cK[t] = ck; cH[t] = ch;
    __syncthreads();
    for (int off = 1; off < 256; off <<= 1) {
        int a = (t >= off) ? cK[t - off] : 0;
        int b2 = (t >= off) ? cH[t - off] : 0;
        __syncthreads();
        cK[t] += a; cH[t] += b2;
        __syncthreads();
    }
    int kb = cK[t] - ck;
    int hb = cH[t] - ch;
#pragma unroll
    for (int e = 0; e < 16; ++e) {
        int m = base + e;
        bool f = byteMode ? (mask8[m] != 0) : (m32[m] != 0u);
        if (f) g_qidx[hb++] = m; else g_kidx[kb++] = m;
    }
    if (t == 255) { g_counts[0] = cK[255]; g_counts[1] = cH[255]; }
}

// ============================================================
// K3: pack gathered operands to bf16 row-major [row][256].
//   grid: (rowtile 0..63, b, which)  which: 0=K(norm lat), 1=V(former), 2=Q(norm lat @qidx)
//   smem transpose: gmem reads coalesced along rows, writes coalesced along d.
// ============================================================
__global__ void k_pack(const float* __restrict__ x) {
    __shared__ float ts[64][65];
    __shared__ int   sIdx[64];
    __shared__ float sSc[64];
    const int b = blockIdx.y, which = blockIdx.z;
    const int row0 = blockIdx.x * 64;
    const int t = threadIdx.x;

    const int cnt = (which == 2) ? g_counts[1] : g_counts[0];
    if (row0 >= ((cnt + 63) & ~63)) return;   // nothing (even padding) needed here

    const int* list = (which == 2) ? g_qidx : g_kidx;
    const float* src = (which == 1) ? (x + (size_t)b * C * N)
                                    : (x + ((size_t)b * C + D) * N);
    __nv_bfloat16* dst = (which == 0 ? g_K : (which == 1 ? g_V : g_Q))
                         + ((size_t)b * 4096 + row0) * 256;

    if (t < 64) {
        int r = row0 + t;
        int m = (r < cnt) ? list[r] : -1;
        sIdx[t] = m;
        sSc[t] = (m >= 0) ? ((which == 1) ? 1.f : g_invnorm[b * N + m]) : 0.f;
    }
    __syncthreads();

    for (int dc = 0; dc < 4; ++dc) {
#pragma unroll
        for (int j = 0; j < 16; ++j) {
            int idx = t + 256 * j;
            int row = idx & 63, dd = idx >> 6;
            int m = sIdx[row];
            ts[dd][row] = (m >= 0) ? src[(size_t)(dc * 64 + dd) * N + m] * sSc[row] : 0.f;
        }
        __syncthreads();
#pragma unroll
        for (int j = 0; j < 16; ++j) {
            int idx = t + 256 * j;
            int dd = idx & 63, row = idx >> 6;
            dst[(size_t)row * 256 + dc * 64 + dd] = __float2bfloat16(ts[dd][row]);
        }
        __syncthreads();
    }
}

// ============================================================
// K4: mma flash attention (fixed softmax max = 1, cos <= 1).
//   CTA: 64 hole queries x one batch. 8 warps: wq=warp>>1 (16-row band),
//   wk=warp&1 (key half for S / d half for PV).
//   smem (bytes): Q 32K | K x2 64K | V x2 64K | P 8K | rowsum | qn
//   All bf16 tiles [row][256] with 16B-chunk XOR swizzle: chunk^(row&7).
// ============================================================
#define SMQ   0
#define SMK0  32768
#define SMV0  98304
#define SMP   163840
#define SMRS  172032
#define SMQN  172544
#define ATTN_SMEM 172800

__global__ __launch_bounds__(256, 1)
void k_attn(const float* __restrict__ x, float* __restrict__ out) {
    extern __shared__ char smc[];
    const uint32_t sb = smaddr(smc);
    const int t = threadIdx.x;
    const int lane = t & 31, w = t >> 5;
    const int wq = w >> 1, wk = w & 1;
    const int b = blockIdx.y, qt = blockIdx.x;

    const int nKnown = g_counts[0];
    const int nHole  = g_counts[1];
    const int q0 = qt * 64;
    if (q0 >= nHole) return;
    const int nQ = min(64, nHole - q0);

    int*   sQn    = (int*)(smc + SMQN);
    float* rowsum = (float*)(smc + SMRS);
    if (t < 64) sQn[t] = (t < nQ) ? g_qidx[q0 + t] : -1;

    // ---- prefetch Q tile + K/V tile 0 (one cp.async group) ----
    const __nv_bfloat16* gq = g_Q + ((size_t)b * 4096 + q0) * 256;
    const __nv_bfloat16* gk = g_K + (size_t)b * 4096 * 256;
    const __nv_bfloat16* gv = g_V + (size_t)b * 4096 * 256;
#pragma unroll
    for (int i = t; i < 2048; i += 256) {
        int row = i >> 5, ch = i & 31;
        uint32_t so = (uint32_t)((row * 32 + (ch ^ (row & 7))) << 4);
        cpasync16(sb + SMQ + so, gq + row * 256 + ch * 8);
        cpasync16(sb + SMK0 + so, gk + row * 256 + ch * 8);
        cpasync16(sb + SMV0 + so, gv + row * 256 + ch * 8);
    }
    asm volatile("cp.async.commit_group;");

    float O[16][4];
#pragma unroll
    for (int i = 0; i < 16; ++i) { O[i][0] = O[i][1] = O[i][2] = O[i][3] = 0.f; }
    float rs0 = 0.f, rs1 = 0.f;

    const int band = wq * 16;
    const int r15 = lane & 15, chalf = lane >> 4;   // A-frag lane mapping
    const int l8 = lane & 7, sel = lane >> 3;       // B-frag lane mapping

    const int nkt = (nKnown + 63) >> 6;
    for (int kt = 0; kt < nkt; ++kt) {
        asm volatile("cp.async.wait_group 0;" ::: "memory");
        __syncthreads();
        const int buf = kt & 1;
        const uint32_t smk = sb + SMK0 + buf * 32768;
        const uint32_t smv = sb + SMV0 + buf * 32768;

        if (kt + 1 < nkt) {  // prefetch next tile into the other buffer
            const __nv_bfloat16* gkt = gk + (size_t)(kt + 1) * 64 * 256;
            const __nv_bfloat16* gvt = gv + (size_t)(kt + 1) * 64 * 256;
            const uint32_t dk = sb + SMK0 + (buf ^ 1) * 32768;
            const uint32_t dv = sb + SMV0 + (buf ^ 1) * 32768;
#pragma unroll
            for (int i = t; i < 2048; i += 256) {
                int row = i >> 5, ch = i & 31;
                uint32_t so = (uint32_t)((row * 32 + (ch ^ (row & 7))) << 4);
                cpasync16(dk + so, gkt + row * 256 + ch * 8);
                cpasync16(dv + so, gvt + row * 256 + ch * 8);
            }
            asm volatile("cp.async.commit_group;");
        }

        // ---- S = Q K^T : warp computes 16q x 32k ----
        float s[4][4];
#pragma unroll
        for (int j = 0; j < 4; ++j) { s[j][0] = s[j][1] = s[j][2] = s[j][3] = 0.f; }
#pragma unroll
        for (int ds = 0; ds < 16; ++ds) {
            uint32_t a[4];
            {
                int row = band + r15, dd = ds * 16 + chalf * 8;
                ldsm4(a, sb + SMQ + (uint32_t)((row * 32 + ((dd >> 3) ^ (row & 7))) << 4));
            }
            uint32_t bb[8];
#pragma unroll
            for (int h = 0; h < 2; ++h) {
                int row = wk * 32 + h * 16 + (sel >> 1) * 8 + l8;
                int dd = ds * 16 + (sel & 1) * 8;
                ldsm4(bb + h * 4, smk + (uint32_t)((row * 32 + ((dd >> 3) ^ (row & 7))) << 4));
            }
            mma_bf16(s[0], a, bb[0], bb[1]);
            mma_bf16(s[1], a, bb[2], bb[3]);
            mma_bf16(s[2], a, bb[4], bb[5]);
            mma_bf16(s[3], a, bb[6], bb[7]);
        }

        // ---- P = exp(S - 1) (cos <= 1 -> fixed max), mask pad, row sums, store bf16 ----
        const int kbase = kt * 64 + wk * 32;
        const int row0 = band + (lane >> 2);
        const int row1 = row0 + 8;
#pragma unroll
        for (int j = 0; j < 4; ++j) {
            int keyg = kbase + j * 8 + (lane & 3) * 2;
            float p0 = __expf(s[j][0] - 1.f), p1 = __expf(s[j][1] - 1.f);
            float p2 = __expf(s[j][2] - 1.f), p3 = __expf(s[j][3] - 1.f);
            if (keyg >= nKnown)     { p0 = 0.f; p2 = 0.f; }
            if (keyg + 1 >= nKnown) { p1 = 0.f; p3 = 0.f; }
            rs0 += p0 + p1;
            rs1 += p2 + p3;
            int col = wk * 32 + j * 8 + (lane & 3) * 2;
            uint32_t o0 = (uint32_t)(row0 * 128 + (((col >> 3) ^ (row0 & 7)) << 4) + ((col & 7) << 1));
            uint32_t o1 = (uint32_t)(row1 * 128 + (((col >> 3) ^ (row1 & 7)) << 4) + ((col & 7) << 1));
            *(__nv_bfloat162*)(smc + SMP + o0) = __floats2bfloat162_rn(p0, p1);
            *(__nv_bfloat162*)(smc + SMP + o1) = __floats2bfloat162_rn(p2, p3);
        }
        __syncthreads();

        // ---- O += P V : warp computes 16q x 128d (d half = wk) ----
#pragma unroll
        for (int ks = 0; ks < 4; ++ks) {
            uint32_t a[4];
            {
                int row = band + r15, kk = ks * 16 + chalf * 8;
                ldsm4(a, sb + SMP + (uint32_t)(row * 128 + (((kk >> 3) ^ (row & 7)) << 4)));
            }
#pragma unroll
            for (int np = 0; np < 8; ++np) {
                int d0 = wk * 128 + np * 16;
                int row = ks * 16 + (sel & 1) * 8 + l8;
                int dd = d0 + (sel >> 1) * 8;
                uint32_t v[4];
                ldsm4t(v, smv + (uint32_t)((row * 32 + ((dd >> 3) ^ (row & 7))) << 4));
                mma_bf16(O[np * 2],     a, v[0], v[1]);
                mma_bf16(O[np * 2 + 1], a, v[2], v[3]);
            }
        }
    }

    // ---- combine row sums across the two wk warps ----
    rs0 += __shfl_xor_sync(0xffffffffu, rs0, 1);
    rs0 += __shfl_xor_sync(0xffffffffu, rs0, 2);
    rs1 += __shfl_xor_sync(0xffffffffu, rs1, 1);
    rs1 += __shfl_xor_sync(0xffffffffu, rs1, 2);
    const int qr0 = band + (lane >> 2), qr1 = qr0 + 8;
    if ((lane & 3) == 0) {
        rowsum[qr0 * 2 + wk] = rs0;
        rowsum[qr1 * 2 + wk] = rs1;
    }
    __syncthreads();

    const float il0 = 1.f / (rowsum[qr0 * 2] + rowsum[qr0 * 2 + 1]);
    const float il1 = 1.f / (rowsum[qr1 * 2] + rowsum[qr1 * 2 + 1]);
    const int n0 = (qr0 < nQ) ? sQn[qr0] : -1;
    const int n1 = (qr1 < nQ) ? sQn[qr1] : -1;
    float* ob = out + ((size_t)b * OUTC + 2 * D) * N;
#pragma unroll
    for (int nt = 0; nt < 16; ++nt) {
        int d0 = wk * 128 + nt * 8 + (lane & 3) * 2;
        if (n0 >= 0) {
            ob[(size_t)d0 * N + n0]       = O[nt][0] * il0;
            ob[(size_t)(d0 + 1) * N + n0] = O[nt][1] * il0;
        }
        if (n1 >= 0) {
            ob[(size_t)d0 * N + n1]       = O[nt][2] * il1;
            ob[(size_t)(d0 + 1) * N + n1] = O[nt][3] * il1;
        }
    }
}

// ============================================================
extern "C" void kernel_launch(void* const* d_in, const int* in_sizes, int n_in,
                              void* d_out, int out_size) {
    const float* x = (const float*)d_in[0];
    const unsigned char* mask = (const unsigned char*)d_in[1];
    float* out = (float*)d_out;
    (void)in_sizes; (void)n_in; (void)out_size;

    k_copy_expand<<<(B * OUTC * N / 4) / 256, 256>>>((const float4*)x, (float4*)out);
    k_invnorm<<<dim3(N / 128, B), 128>>>(x);
    k_build_lists<<<1, 256>>>(mask);
    k_pack<<<dim3(64, B, 3), 256>>>(x);

    cudaFuncSetAttribute(k_attn, cudaFuncAttributeMaxDynamicSharedMemorySize, ATTN_SMEM);
    k_attn<<<dim3(64, B), 256, ATTN_SMEM>>>(x, out);
}

// round 9
// speedup vs baseline: 8.7185x; 1.0798x over previous
#include <cuda_runtime.h>
#include <cuda_bf16.h>
#include <math.h>
#include <stdint.h>

// Problem constants (fixed shapes: x [8,512,64,64] fp32, mask [64,64] bool)
#define B 8
#define C 512
#define D 256              // C/2
#define N 4096             // 64*64
#define OUTC 768           // 3*D

// ---- device scratch (no allocation allowed) ----
__device__ float g_invnorm[B * N];
__device__ int   g_kidx[N];     // known (unmasked) pixel indices, ascending
__device__ int   g_qidx[N];     // hole (masked) pixel indices, ascending
__device__ int   g_counts[2];   // [0]=nKnown, [1]=nHole

// packed bf16 operands: [b][row][256] row-major (row = compact index)
__device__ __align__(256) __nv_bfloat16 g_K[(size_t)B * 4096 * 256];
__device__ __align__(256) __nv_bfloat16 g_V[(size_t)B * 4096 * 256];
__device__ __align__(256) __nv_bfloat16 g_Q[(size_t)B * 4096 * 256];

// ============================================================
// PTX helpers (legacy mma path only — tcgen05 not supported by
// this toolchain's ptxas target, confirmed R8)
// ============================================================
__device__ __forceinline__ uint32_t smaddr(const void* p) {
    return (uint32_t)__cvta_generic_to_shared(p);
}
__device__ __forceinline__ void ldsm4(uint32_t* r, uint32_t a) {
    asm volatile("ldmatrix.sync.aligned.m8n8.x4.shared.b16 {%0,%1,%2,%3}, [%4];"
        : "=r"(r[0]), "=r"(r[1]), "=r"(r[2]), "=r"(r[3]) : "r"(a));
}
__device__ __forceinline__ void ldsm4t(uint32_t* r, uint32_t a) {
    asm volatile("ldmatrix.sync.aligned.m8n8.x4.trans.shared.b16 {%0,%1,%2,%3}, [%4];"
        : "=r"(r[0]), "=r"(r[1]), "=r"(r[2]), "=r"(r[3]) : "r"(a));
}
__device__ __forceinline__ void mma_bf16(float* c, const uint32_t* a, uint32_t b0, uint32_t b1) {
    asm volatile("mma.sync.aligned.m16n8k16.row.col.f32.bf16.bf16.f32 "
        "{%0,%1,%2,%3}, {%4,%5,%6,%7}, {%8,%9}, {%0,%1,%2,%3};"
        : "+f"(c[0]), "+f"(c[1]), "+f"(c[2]), "+f"(c[3])
        : "r"(a[0]), "r"(a[1]), "r"(a[2]), "r"(a[3]), "r"(b0), "r"(b1));
}
__device__ __forceinline__ void cpasync16(uint32_t s, const void* g) {
    asm volatile("cp.async.cg.shared.global [%0], [%1], 16;" :: "r"(s), "l"(g));
}
__device__ __forceinline__ uint32_t packbf2(float lo, float hi) {
    __nv_bfloat162 h = __floats2bfloat162_rn(lo, hi);
    return *(uint32_t*)&h;
}

// ============================================================
// K0: copy former+latter into out channels [0,512), zero [512,768).
// ============================================================
__global__ void k_copy_expand(const float4* __restrict__ x4, float4* __restrict__ o4) {
    int i = blockIdx.x * 256 + threadIdx.x;           // < 6291456
    int b = i / (OUTC * N / 4);
    int r = i - b * (OUTC * N / 4);
    float4 v;
    if (r < C * N / 4) v = x4[b * (C * N / 4) + r];
    else               v = make_float4(0.f, 0.f, 0.f, 0.f);
    o4[i] = v;
}

// ============================================================
// K1: inv-norm of latter per (b, n)
// ============================================================
__global__ void k_invnorm(const float* __restrict__ x) {
    int b = blockIdx.y;
    int n = blockIdx.x * 128 + threadIdx.x;
    const float* p = x + ((size_t)b * C + D) * N + n;
    float s = 0.f;
#pragma unroll 8
    for (int d = 0; d < D; ++d) {
        float v = p[(size_t)d * N];
        s = fmaf(v, v, s);
    }
    g_invnorm[b * N + n] = 1.0f / (sqrtf(s) + 1e-8f);
}

// ============================================================
// K2: build compact index lists (verified correct since R4)
// ============================================================
__global__ void k_build_lists(const unsigned char* __restrict__ mask8) {
    __shared__ int cK[256], cH[256];
    __shared__ int byteEvidence;
    const int t = threadIdx.x;
    if (t == 0) byteEvidence = 0;
    __syncthreads();

    const unsigned int* m32 = (const unsigned int*)mask8;
    int bad = 0;
    for (int w = t; w < 1024; w += 256) {
        unsigned int v = m32[w];
        if (v != 0u && v != 1u && v != 0x3F800000u) bad = 1;
    }
    if (bad) byteEvidence = 1;
    __syncthreads();
    const bool byteMode = (byteEvidence != 0);

    const int base = t * 16;
    int ck = 0, ch = 0;
#pragma unroll
    for (int e = 0; e < 16; ++e) {
        int m = base + e;
        bool f = byteMode ? (mask8[m] != 0) : (m32[m] != 0u);
        if (f) ch++; else ck++;
    }
    cK[t] = ck; cH[t] = ch;
    __syncthreads();
    for (int off = 1; off < 256; off <<= 1) {
        int a = (t >= off) ? cK[t - off] : 0;
        int b2 = (t >= off) ? cH[t - off] : 0;
        __syncthreads();
        cK[t] += a; cH[t] += b2;
        __syncthreads();
    }
    int kb = cK[t] - ck;
    int hb = cH[t] - ch;
#pragma unroll
    for (int e = 0; e < 16; ++e) {
        int m = base + e;
        bool f = byteMode ? (mask8[m] != 0) : (m32[m] != 0u);
        if (f) g_qidx[hb++] = m; else g_kidx[kb++] = m;
    }
    if (t == 255) { g_counts[0] = cK[255]; g_counts[1] = cH[255]; }
}

// ============================================================
// K3: pack gathered operands to bf16 row-major [row][256].
//   which: 0=K(norm latter), 1=V(former), 2=Q(norm latter @qidx)
//   Full 64x256 tile staged in smem: ONE load phase (64 independent
//   gathered loads per thread -> deep MLP), one sync, coalesced stores.
// ============================================================
#define PACK_SMEM (256 * 65 * 4)   // 66560 B, ts[dd][row], row pitch 65

__global__ void k_pack(const float* __restrict__ x) {
    extern __shared__ float ts[];            // [256][65]
    __shared__ int   sIdx[64];
    __shared__ float sSc[64];
    const int b = blockIdx.y, which = blockIdx.z;
    const int row0 = blockIdx.x * 64;
    const int t = threadIdx.x;

    const int cnt = (which == 2) ? g_counts[1] : g_counts[0];
    if (row0 >= ((cnt + 63) & ~63)) return;

    const int* list = (which == 2) ? g_qidx : g_kidx;
    const float* src = (which == 1) ? (x + (size_t)b * C * N)
                                    : (x + ((size_t)b * C + D) * N);
    __nv_bfloat16* dst = (which == 0 ? g_K : (which == 1 ? g_V : g_Q))
                         + ((size_t)b * 4096 + row0) * 256;

    if (t < 64) {
        int r = row0 + t;
        int m = (r < cnt) ? list[r] : -1;
        sIdx[t] = m;
        sSc[t] = (m >= 0) ? ((which == 1) ? 1.f : g_invnorm[b * N + m]) : 0.f;
    }
    __syncthreads();

    // load phase: idx = t + 256*j ; row = idx&63 (coalesced-ish gather), dd = idx>>6
#pragma unroll 8
    for (int j = 0; j < 64; ++j) {
        int idx = t + 256 * j;
        int row = idx & 63, dd = idx >> 6;
        int m = sIdx[row];
        ts[dd * 65 + row] = (m >= 0) ? src[(size_t)dd * N + m] * sSc[row] : 0.f;
    }
    __syncthreads();
    // store phase: idx = t + 256*j ; dd = idx&255 (coalesced store), row = idx>>8
#pragma unroll 8
    for (int j = 0; j < 64; ++j) {
        int idx = t + 256 * j;
        int dd = idx & 255, row = idx >> 8;
        dst[(size_t)row * 256 + dd] = __float2bfloat16(ts[dd * 65 + row]);
    }
}

// ============================================================
// K4: mma flash attention, register-resident P.
//   CTA = 128 hole queries x 1 batch, 8 warps, warp w owns rows [w*16,w*16+16).
//   Per 64-key tile: S(16x64) -> exp in regs -> C-frags reused as A-frags
//   -> PV(16x256). No smem P; 2 syncthreads per tile (buffer handoff only).
//   smem: Q 64K | K x2 64K | V x2 64K | qn. Tiles [row][256] bf16,
//   16B-chunk XOR swizzle: chunk ^ (row&7).
// ============================================================
#define SQ_   0
#define SK0_  65536
#define SK1_  98304
#define SV0_  131072
#define SV1_  163840
#define SQN_  196608
#define ATTN_SMEM 197120

__device__ __forceinline__ uint32_t sw_addr(int row, int dd) {  // dd multiple of 8
    return (uint32_t)((row * 32 + ((dd >> 3) ^ (row & 7))) << 4);
}

__global__ __launch_bounds__(256, 1)
void k_attn(float* __restrict__ out) {
    extern __shared__ char smc[];
    const uint32_t sb = smaddr(smc);
    const int t = threadIdx.x;
    const int lane = t & 31, w = t >> 5;
    const int b = blockIdx.y, qt = blockIdx.x;

    const int nKnown = g_counts[0];
    const int nHole  = g_counts[1];
    const int q0 = qt * 128;
    if (q0 >= nHole) return;
    const int nQ = min(128, nHole - q0);
    const int nkt = (nKnown + 63) >> 6;

    int* sQn = (int*)(smc + SQN_);
    if (t < 128) sQn[t] = (t < nQ) ? g_qidx[q0 + t] : -1;

    const __nv_bfloat16* gq = g_Q + ((size_t)b * 4096 + q0) * 256;
    const __nv_bfloat16* gk = g_K + (size_t)b * 4096 * 256;
    const __nv_bfloat16* gv = g_V + (size_t)b * 4096 * 256;

    // ---- prologue: Q + tile0 in group0; tile1 in group1 ----
#pragma unroll 4
    for (int i = t; i < 4096; i += 256) {   // Q: 128 rows x 32 chunks
        int row = i >> 5, ch = i & 31;
        cpasync16(sb + SQ_ + sw_addr(row, ch << 3), gq + row * 256 + ch * 8);
    }
#define LOAD_KV(kt_, kb_, vb_) do { \
    for (int i = t; i < 2048; i += 256) { \
        int row = i >> 5, ch = i & 31; \
        uint32_t so = sw_addr(row, ch << 3); \
        cpasync16((kb_) + so, gk + (size_t)((kt_) * 64 + row) * 256 + ch * 8); \
        cpasync16((vb_) + so, gv + (size_t)((kt_) * 64 + row) * 256 + ch * 8); \
    } \
} while (0)

    LOAD_KV(0, sb + SK0_, sb + SV0_);
    asm volatile("cp.async.commit_group;");
    if (nkt > 1) { LOAD_KV(1, sb + SK1_, sb + SV1_); asm volatile("cp.async.commit_group;"); }

    float O[32][4];
#pragma unroll
    for (int i = 0; i < 32; ++i) { O[i][0] = O[i][1] = O[i][2] = O[i][3] = 0.f; }
    float rs0 = 0.f, rs1 = 0.f;

    const int band = w * 16;
    const int r15 = lane & 15, chalf = lane >> 4;   // A-frag mapping
    const int l8 = lane & 7, sel = lane >> 3;       // B-frag mapping

    for (int kt = 0; kt < nkt; ++kt) {
        // groups committed so far: min(kt+2, nkt); need group kt+1 complete
        if (kt + 2 <= nkt - 1)      // a newer (kt+1 prefetched later) group may exist
            asm volatile("cp.async.wait_group 1;" ::: "memory");
        else if (kt + 1 < nkt)
            asm volatile("cp.async.wait_group 1;" ::: "memory");
        else
            asm volatile("cp.async.wait_group 0;" ::: "memory");
        __syncthreads();
        const uint32_t smk = sb + ((kt & 1) ? SK1_ : SK0_);
        const uint32_t smv = sb + ((kt & 1) ? SV1_ : SV0_);

        // ---- S = Q K^T : 16q x 64k ----
        float s[8][4];
#pragma unroll
        for (int j = 0; j < 8; ++j) { s[j][0] = s[j][1] = s[j][2] = s[j][3] = 0.f; }
#pragma unroll
        for (int ds = 0; ds < 16; ++ds) {
            uint32_t a[4];
            ldsm4(a, sb + SQ_ + sw_addr(band + r15, ds * 16 + chalf * 8));
#pragma unroll
            for (int g = 0; g < 4; ++g) {
                uint32_t bb[4];
                ldsm4(bb, smk + sw_addr(g * 16 + (sel >> 1) * 8 + l8, ds * 16 + (sel & 1) * 8));
                mma_bf16(s[2 * g],     a, bb[0], bb[1]);
                mma_bf16(s[2 * g + 1], a, bb[2], bb[3]);
            }
        }

        // ---- P = exp(S-1) in regs, mask pad keys, repack C-frags -> A-frags ----
        uint32_t pa[4][4];
        const int kg = kt * 64 + (lane & 3) * 2;
#pragma unroll
        for (int j = 0; j < 8; ++j) {
            float p0 = __expf(s[j][0] - 1.f), p1 = __expf(s[j][1] - 1.f);
            float p2 = __expf(s[j][2] - 1.f), p3 = __expf(s[j][3] - 1.f);
            int keyg = kg + j * 8;
            if (keyg >= nKnown)     { p0 = 0.f; p2 = 0.f; }
            if (keyg + 1 >= nKnown) { p1 = 0.f; p3 = 0.f; }
            rs0 += p0 + p1;
            rs1 += p2 + p3;
            pa[j >> 1][(j & 1) * 2]     = packbf2(p0, p1);   // a0 / a2
            pa[j >> 1][(j & 1) * 2 + 1] = packbf2(p2, p3);   // a1 / a3
        }

        // ---- O += P V : 16q x 256d ----
#pragma unroll
        for (int ks = 0; ks < 4; ++ks) {
#pragma unroll
            for (int np = 0; np < 16; ++np) {
                uint32_t v[4];
                ldsm4t(v, smv + sw_addr(ks * 16 + (sel & 1) * 8 + l8, np * 16 + (sel >> 1) * 8));
                mma_bf16(O[2 * np],     pa[ks], v[0], v[1]);
                mma_bf16(O[2 * np + 1], pa[ks], v[2], v[3]);
            }
        }

        __syncthreads();   // all warps done reading buffer kt&1
        if (kt + 2 < nkt) {
            const uint32_t kb_ = sb + ((kt & 1) ? SK1_ : SK0_);
            const uint32_t vb_ = sb + ((kt & 1) ? SV1_ : SV0_);
            LOAD_KV(kt + 2, kb_, vb_);
            asm volatile("cp.async.commit_group;");
        }
    }

    // ---- rowsum reduction within quad, normalize, scatter ----
    rs0 += __shfl_xor_sync(0xffffffffu, rs0, 1);
    rs0 += __shfl_xor_sync(0xffffffffu, rs0, 2);
    rs1 += __shfl_xor_sync(0xffffffffu, rs1, 1);
    rs1 += __shfl_xor_sync(0xffffffffu, rs1, 2);
    const float il0 = 1.f / rs0, il1 = 1.f / rs1;
    const int qr0 = band + (lane >> 2), qr1 = qr0 + 8;
    const int n0 = (qr0 < nQ) ? sQn[qr0] : -1;
    const int n1 = (qr1 < nQ) ? sQn[qr1] : -1;
    float* ob = out + ((size_t)b * OUTC + 2 * D) * N;
#pragma unroll
    for (int nt = 0; nt < 32; ++nt) {
        int d0 = nt * 8 + (lane & 3) * 2;
        if (n0 >= 0) {
            ob[(size_t)d0 * N + n0]       = O[nt][0] * il0;
            ob[(size_t)(d0 + 1) * N + n0] = O[nt][1] * il0;
        }
        if (n1 >= 0) {
            ob[(size_t)d0 * N + n1]       = O[nt][2] * il1;
            ob[(size_t)(d0 + 1) * N + n1] = O[nt][3] * il1;
        }
    }
}

// ============================================================
extern "C" void kernel_launch(void* const* d_in, const int* in_sizes, int n_in,
                              void* d_out, int out_size) {
    const float* x = (const float*)d_in[0];
    const unsigned char* mask = (const unsigned char*)d_in[1];
    float* out = (float*)d_out;
    (void)in_sizes; (void)n_in; (void)out_size;

    k_copy_expand<<<(B * OUTC * N / 4) / 256, 256>>>((const float4*)x, (float4*)out);
    k_invnorm<<<dim3(N / 128, B), 128>>>(x);
    k_build_lists<<<1, 256>>>(mask);

    cudaFuncSetAttribute(k_pack, cudaFuncAttributeMaxDynamicSharedMemorySize, PACK_SMEM);
    k_pack<<<dim3(64, B, 3), 256, PACK_SMEM>>>(x);

    cudaFuncSetAttribute(k_attn, cudaFuncAttributeMaxDynamicSharedMemorySize, ATTN_SMEM);
    // 32 q-tiles of 128 cover up to 4096 holes; inactive tiles early-exit
    k_attn<<<dim3(32, B), 256, ATTN_SMEM>>>(out);
}

// round 10
// speedup vs baseline: 11.8276x; 1.3566x over previous
#include <cuda_runtime.h>
#include <cuda_bf16.h>
#include <math.h>
#include <stdint.h>

// Problem constants (fixed shapes: x [8,512,64,64] fp32, mask [64,64] bool)
#define B 8
#define C 512
#define D 256              // C/2
#define N 4096             // 64*64
#define OUTC 768           // 3*D

// ---- device scratch (no allocation allowed) ----
__device__ float g_invnorm[B * N];
__device__ int   g_kidx[N];     // known (unmasked) pixel indices, ascending
__device__ int   g_qidx[N];     // hole (masked) pixel indices, ascending
__device__ int   g_counts[2];   // [0]=nKnown, [1]=nHole

// packed bf16 operands: [b][row][256] row-major (row = compact index)
__device__ __align__(256) __nv_bfloat16 g_K[(size_t)B * 4096 * 256];
__device__ __align__(256) __nv_bfloat16 g_V[(size_t)B * 4096 * 256];
__device__ __align__(256) __nv_bfloat16 g_Q[(size_t)B * 4096 * 256];

// ============================================================
// PTX helpers (legacy mma path — tcgen05 rejected by this
// toolchain's ptxas target, confirmed R8)
// ============================================================
__device__ __forceinline__ uint32_t smaddr(const void* p) {
    return (uint32_t)__cvta_generic_to_shared(p);
}
__device__ __forceinline__ void ldsm4(uint32_t* r, uint32_t a) {
    asm volatile("ldmatrix.sync.aligned.m8n8.x4.shared.b16 {%0,%1,%2,%3}, [%4];"
        : "=r"(r[0]), "=r"(r[1]), "=r"(r[2]), "=r"(r[3]) : "r"(a));
}
__device__ __forceinline__ void ldsm4t(uint32_t* r, uint32_t a) {
    asm volatile("ldmatrix.sync.aligned.m8n8.x4.trans.shared.b16 {%0,%1,%2,%3}, [%4];"
        : "=r"(r[0]), "=r"(r[1]), "=r"(r[2]), "=r"(r[3]) : "r"(a));
}
__device__ __forceinline__ void mma_bf16(float* c, const uint32_t* a, uint32_t b0, uint32_t b1) {
    asm volatile("mma.sync.aligned.m16n8k16.row.col.f32.bf16.bf16.f32 "
        "{%0,%1,%2,%3}, {%4,%5,%6,%7}, {%8,%9}, {%0,%1,%2,%3};"
        : "+f"(c[0]), "+f"(c[1]), "+f"(c[2]), "+f"(c[3])
        : "r"(a[0]), "r"(a[1]), "r"(a[2]), "r"(a[3]), "r"(b0), "r"(b1));
}
__device__ __forceinline__ void cpasync16(uint32_t s, const void* g) {
    asm volatile("cp.async.cg.shared.global [%0], [%1], 16;" :: "r"(s), "l"(g));
}
__device__ __forceinline__ void cpasync4(uint32_t s, const void* g) {
    asm volatile("cp.async.ca.shared.global [%0], [%1], 4;" :: "r"(s), "l"(g));
}
__device__ __forceinline__ uint32_t packbf2(float lo, float hi) {
    __nv_bfloat162 h = __floats2bfloat162_rn(lo, hi);
    return *(uint32_t*)&h;
}

// ============================================================
// K0: copy former+latter into out channels [0,512), zero [512,768).
// ============================================================
__global__ void k_copy_expand(const float4* __restrict__ x4, float4* __restrict__ o4) {
    int i = blockIdx.x * 256 + threadIdx.x;           // < 6291456
    int b = i / (OUTC * N / 4);
    int r = i - b * (OUTC * N / 4);
    float4 v;
    if (r < C * N / 4) v = x4[b * (C * N / 4) + r];
    else               v = make_float4(0.f, 0.f, 0.f, 0.f);
    o4[i] = v;
}

// ============================================================
// K1: inv-norm of latter per (b, n)
// ============================================================
__global__ void k_invnorm(const float* __restrict__ x) {
    int b = blockIdx.y;
    int n = blockIdx.x * 128 + threadIdx.x;
    const float* p = x + ((size_t)b * C + D) * N + n;
    float s = 0.f;
#pragma unroll 8
    for (int d = 0; d < D; ++d) {
        float v = p[(size_t)d * N];
        s = fmaf(v, v, s);
    }
    g_invnorm[b * N + n] = 1.0f / (sqrtf(s) + 1e-8f);
}

// ============================================================
// K2: build compact index lists (verified correct since R4)
// ============================================================
__global__ void k_build_lists(const unsigned char* __restrict__ mask8) {
    __shared__ int cK[256], cH[256];
    __shared__ int byteEvidence;
    const int t = threadIdx.x;
    if (t == 0) byteEvidence = 0;
    __syncthreads();

    const unsigned int* m32 = (const unsigned int*)mask8;
    int bad = 0;
    for (int w = t; w < 1024; w += 256) {
        unsigned int v = m32[w];
        if (v != 0u && v != 1u && v != 0x3F800000u) bad = 1;
    }
    if (bad) byteEvidence = 1;
    __syncthreads();
    const bool byteMode = (byteEvidence != 0);

    const int base = t * 16;
    int ck = 0, ch = 0;
#pragma unroll
    for (int e = 0; e < 16; ++e) {
        int m = base + e;
        bool f = byteMode ? (mask8[m] != 0) : (m32[m] != 0u);
        if (f) ch++; else ck++;
    }
    cK[t] = ck; cH[t] = ch;
    __syncthreads();
    for (int off = 1; off < 256; off <<= 1) {
        int a = (t >= off) ? cK[t - off] : 0;
        int b2 = (t >= off) ? cH[t - off] : 0;
        __syncthreads();
        cK[t] += a; cH[t] += b2;
        __syncthreads();
    }
    int kb = cK[t] - ck;
    int hb = cH[t] - ch;
#pragma unroll
    for (int e = 0; e < 16; ++e) {
        int m = base + e;
        bool f = byteMode ? (mask8[m] != 0) : (m32[m] != 0u);
        if (f) g_qidx[hb++] = m; else g_kidx[kb++] = m;
    }
    if (t == 255) { g_counts[0] = cK[255]; g_counts[1] = cH[255]; }
}

// ============================================================
// K3: pack gathered operands to bf16 row-major [row][256].
//   which: 0=K(norm latter), 1=V(former), 2=Q(norm latter @qidx)
//   Gather via cp.async.ca 4B (LDGSTS: no register dependency ->
//   deep MLP regardless of regcount); scale+convert in the
//   conflict-free coalesced store phase. Invalid rows: safe dummy
//   address + scale 0.
// ============================================================
#define PACK_SMEM (256 * 65 * 4)   // 66560 B, ts[dd][row], row pitch 65

__global__ void k_pack(const float* __restrict__ x) {
    extern __shared__ float ts[];            // [256][65]
    __shared__ int   sIdx[64];
    __shared__ float sSc[64];
    const int b = blockIdx.y, which = blockIdx.z;
    const int row0 = blockIdx.x * 64;
    const int t = threadIdx.x;

    const int cnt = (which == 2) ? g_counts[1] : g_counts[0];
    if (row0 >= ((cnt + 63) & ~63)) return;

    const int* list = (which == 2) ? g_qidx : g_kidx;
    const float* src = (which == 1) ? (x + (size_t)b * C * N)
                                    : (x + ((size_t)b * C + D) * N);
    __nv_bfloat16* dst = (which == 0 ? g_K : (which == 1 ? g_V : g_Q))
                         + ((size_t)b * 4096 + row0) * 256;

    if (t < 64) {
        int r = row0 + t;
        int m = (r < cnt) ? list[r] : -1;
        sIdx[t] = (m >= 0) ? m : 0;                     // safe dummy addr for pads
        sSc[t] = (m >= 0) ? ((which == 1) ? 1.f : g_invnorm[b * N + m]) : 0.f;
    }
    __syncthreads();

    // gather phase: idx = t + 256*j ; row = idx&63, dd = idx>>6
    const uint32_t tsb = smaddr(ts);
#pragma unroll 16
    for (int j = 0; j < 64; ++j) {
        int idx = t + 256 * j;
        int row = idx & 63, dd = idx >> 6;
        cpasync4(tsb + (uint32_t)((dd * 65 + row) << 2),
                 src + (size_t)dd * N + sIdx[row]);
    }
    asm volatile("cp.async.commit_group;");
    asm volatile("cp.async.wait_group 0;" ::: "memory");
    __syncthreads();

    // store phase: thread t owns column dd=t; row=j. reads stride-65 (conflict-free),
    // writes coalesced. Scale applied here.
#pragma unroll 16
    for (int j = 0; j < 64; ++j) {
        dst[(size_t)j * 256 + t] = __float2bfloat16(ts[t * 65 + j] * sSc[j]);
    }
}

// ============================================================
// K4: mma flash attention, register-resident P.
//   CTA = 64 hole queries x 1 batch, 4 warps (16 rows each), 128 thr.
//   Grid 16x8 = 128 CTAs -> ~all SMs busy (R9 had 64 CTAs: half idle).
//   Per 64-key tile: S(16x64) -> exp in regs -> C-frags reused as
//   A-frags -> PV(16x256). 2 syncthreads/tile (buffer handoff only).
//   smem: Q 32K | K x2 64K | V x2 64K | qn. Tiles [row][256] bf16,
//   16B-chunk XOR swizzle: chunk ^ (row&7).
// ============================================================
#define SQ_   0
#define SK0_  32768
#define SK1_  65536
#define SV0_  98304
#define SV1_  131072
#define SQN_  163840
#define ATTN_SMEM 164352

__device__ __forceinline__ uint32_t sw_addr(int row, int dd) {  // dd multiple of 8
    return (uint32_t)((row * 32 + ((dd >> 3) ^ (row & 7))) << 4);
}

__global__ __launch_bounds__(128, 1)
void k_attn(float* __restrict__ out) {
    extern __shared__ char smc[];
    const uint32_t sb = smaddr(smc);
    const int t = threadIdx.x;
    const int lane = t & 31, w = t >> 5;       // w in 0..3
    const int b = blockIdx.y, qt = blockIdx.x;

    const int nKnown = g_counts[0];
    const int nHole  = g_counts[1];
    const int q0 = qt * 64;
    if (q0 >= nHole) return;
    const int nQ = min(64, nHole - q0);
    const int nkt = (nKnown + 63) >> 6;

    int* sQn = (int*)(smc + SQN_);
    if (t < 64) sQn[t] = (t < nQ) ? g_qidx[q0 + t] : -1;

    const __nv_bfloat16* gq = g_Q + ((size_t)b * 4096 + q0) * 256;
    const __nv_bfloat16* gk = g_K + (size_t)b * 4096 * 256;
    const __nv_bfloat16* gv = g_V + (size_t)b * 4096 * 256;

    // ---- prologue: Q + tile0 in group0; tile1 in group1 ----
#pragma unroll 4
    for (int i = t; i < 2048; i += 128) {   // Q: 64 rows x 32 chunks
        int row = i >> 5, ch = i & 31;
        cpasync16(sb + SQ_ + sw_addr(row, ch << 3), gq + row * 256 + ch * 8);
    }
#define LOAD_KV(kt_, kb_, vb_) do { \
    for (int i = t; i < 2048; i += 128) { \
        int row = i >> 5, ch = i & 31; \
        uint32_t so = sw_addr(row, ch << 3); \
        cpasync16((kb_) + so, gk + (size_t)((kt_) * 64 + row) * 256 + ch * 8); \
        cpasync16((vb_) + so, gv + (size_t)((kt_) * 64 + row) * 256 + ch * 8); \
    } \
} while (0)

    LOAD_KV(0, sb + SK0_, sb + SV0_);
    asm volatile("cp.async.commit_group;");
    if (nkt > 1) { LOAD_KV(1, sb + SK1_, sb + SV1_); asm volatile("cp.async.commit_group;"); }

    float O[32][4];
#pragma unroll
    for (int i = 0; i < 32; ++i) { O[i][0] = O[i][1] = O[i][2] = O[i][3] = 0.f; }
    float rs0 = 0.f, rs1 = 0.f;

    const int band = w * 16;
    const int r15 = lane & 15, chalf = lane >> 4;   // A-frag mapping
    const int l8 = lane & 7, sel = lane >> 3;       // B-frag mapping

    for (int kt = 0; kt < nkt; ++kt) {
        if (kt + 1 < nkt) asm volatile("cp.async.wait_group 1;" ::: "memory");
        else              asm volatile("cp.async.wait_group 0;" ::: "memory");
        __syncthreads();
        const uint32_t smk = sb + ((kt & 1) ? SK1_ : SK0_);
        const uint32_t smv = sb + ((kt & 1) ? SV1_ : SV0_);

        // ---- S = Q K^T : 16q x 64k ----
        float s[8][4];
#pragma unroll
        for (int j = 0; j < 8; ++j) { s[j][0] = s[j][1] = s[j][2] = s[j][3] = 0.f; }
#pragma unroll
        for (int ds = 0; ds < 16; ++ds) {
            uint32_t a[4];
            ldsm4(a, sb + SQ_ + sw_addr(band + r15, ds * 16 + chalf * 8));
#pragma unroll
            for (int g = 0; g < 4; ++g) {
                uint32_t bb[4];
                ldsm4(bb, smk + sw_addr(g * 16 + (sel >> 1) * 8 + l8, ds * 16 + (sel & 1) * 8));
                mma_bf16(s[2 * g],     a, bb[0], bb[1]);
                mma_bf16(s[2 * g + 1], a, bb[2], bb[3]);
            }
        }

        // ---- P = exp(S-1) in regs, mask pad keys, repack C-frags -> A-frags ----
        uint32_t pa[4][4];
        const int kg = kt * 64 + (lane & 3) * 2;
#pragma unroll
        for (int j = 0; j < 8; ++j) {
            float p0 = __expf(s[j][0] - 1.f), p1 = __expf(s[j][1] - 1.f);
            float p2 = __expf(s[j][2] - 1.f), p3 = __expf(s[j][3] - 1.f);
            int keyg = kg + j * 8;
            if (keyg >= nKnown)     { p0 = 0.f; p2 = 0.f; }
            if (keyg + 1 >= nKnown) { p1 = 0.f; p3 = 0.f; }
            rs0 += p0 + p1;
            rs1 += p2 + p3;
            pa[j >> 1][(j & 1) * 2]     = packbf2(p0, p1);   // a0 / a2
            pa[j >> 1][(j & 1) * 2 + 1] = packbf2(p2, p3);   // a1 / a3
        }

        // ---- O += P V : 16q x 256d ----
#pragma unroll
        for (int ks = 0; ks < 4; ++ks) {
#pragma unroll
            for (int np = 0; np < 16; ++np) {
                uint32_t v[4];
                ldsm4t(v, smv + sw_addr(ks * 16 + (sel & 1) * 8 + l8, np * 16 + (sel >> 1) * 8));
                mma_bf16(O[2 * np],     pa[ks], v[0], v[1]);
                mma_bf16(O[2 * np + 1], pa[ks], v[2], v[3]);
            }
        }

        __syncthreads();   // all warps done reading buffer kt&1
        if (kt + 2 < nkt) {
            const uint32_t kb_ = sb + ((kt & 1) ? SK1_ : SK0_);
            const uint32_t vb_ = sb + ((kt & 1) ? SV1_ : SV0_);
            LOAD_KV(kt + 2, kb_, vb_);
            asm volatile("cp.async.commit_group;");
        }
    }

    // ---- rowsum reduction within quad, normalize, scatter ----
    rs0 += __shfl_xor_sync(0xffffffffu, rs0, 1);
    rs0 += __shfl_xor_sync(0xffffffffu, rs0, 2);
    rs1 += __shfl_xor_sync(0xffffffffu, rs1, 1);
    rs1 += __shfl_xor_sync(0xffffffffu, rs1, 2);
    const float il0 = 1.f / rs0, il1 = 1.f / rs1;
    const int qr0 = band + (lane >> 2), qr1 = qr0 + 8;
    const int n0 = (qr0 < nQ) ? sQn[qr0] : -1;
    const int n1 = (qr1 < nQ) ? sQn[qr1] : -1;
    float* ob = out + ((size_t)b * OUTC + 2 * D) * N;
#pragma unroll
    for (int nt = 0; nt < 32; ++nt) {
        int d0 = nt * 8 + (lane & 3) * 2;
        if (n0 >= 0) {
            ob[(size_t)d0 * N + n0]       = O[nt][0] * il0;
            ob[(size_t)(d0 + 1) * N + n0] = O[nt][1] * il0;
        }
        if (n1 >= 0) {
            ob[(size_t)d0 * N + n1]       = O[nt][2] * il1;
            ob[(size_t)(d0 + 1) * N + n1] = O[nt][3] * il1;
        }
    }
}

// ============================================================
extern "C" void kernel_launch(void* const* d_in, const int* in_sizes, int n_in,
                              void* d_out, int out_size) {
    const float* x = (const float*)d_in[0];
    const unsigned char* mask = (const unsigned char*)d_in[1];
    float* out = (float*)d_out;
    (void)in_sizes; (void)n_in; (void)out_size;

    k_copy_expand<<<(B * OUTC * N / 4) / 256, 256>>>((const float4*)x, (float4*)out);
    k_invnorm<<<dim3(N / 128, B), 128>>>(x);
    k_build_lists<<<1, 256>>>(mask);

    cudaFuncSetAttribute(k_pack, cudaFuncAttributeMaxDynamicSharedMemorySize, PACK_SMEM);
    k_pack<<<dim3(64, B, 3), 256, PACK_SMEM>>>(x);

    cudaFuncSetAttribute(k_attn, cudaFuncAttributeMaxDynamicSharedMemorySize, ATTN_SMEM);
    // 64 q-tiles of 64 cover up to 4096 holes; inactive tiles early-exit
    k_attn<<<dim3(64, B), 128, ATTN_SMEM>>>(out);
}

// round 11
// speedup vs baseline: 12.3640x; 1.0453x over previous
#include <cuda_runtime.h>
#include <cuda_bf16.h>
#include <math.h>
#include <stdint.h>

// Problem constants (fixed shapes: x [8,512,64,64] fp32, mask [64,64] bool)
#define B 8
#define C 512
#define D 256              // C/2
#define N 4096             // 64*64
#define OUTC 768           // 3*D

// ---- device scratch (no allocation allowed) ----
__device__ float g_invnorm[B * N];
__device__ int   g_kidx[N];     // known (unmasked) pixel indices, ascending
__device__ int   g_qidx[N];     // hole (masked) pixel indices, ascending
__device__ int   g_rank[N];     // pixel -> hole rank, or -1 if known
__device__ int   g_counts[2];   // [0]=nKnown, [1]=nHole

// packed bf16 operands: [b][row][256] row-major (row = compact index)
__device__ __align__(256) __nv_bfloat16 g_K[(size_t)B * 4096 * 256];
__device__ __align__(256) __nv_bfloat16 g_V[(size_t)B * 4096 * 256];
__device__ __align__(256) __nv_bfloat16 g_Q[(size_t)B * 4096 * 256];

// split-K partials: O [split][b][d][q] (d-major for coalesced reduce reads),
// L [split][b][q]
__device__ __align__(256) float g_pO[(size_t)2 * B * 256 * 4096];
__device__ float g_pL[2 * B * 4096];

// ============================================================
// PTX helpers (legacy mma path — tcgen05 rejected by this
// toolchain's ptxas target, confirmed R8)
// ============================================================
__device__ __forceinline__ uint32_t smaddr(const void* p) {
    return (uint32_t)__cvta_generic_to_shared(p);
}
__device__ __forceinline__ void ldsm4(uint32_t* r, uint32_t a) {
    asm volatile("ldmatrix.sync.aligned.m8n8.x4.shared.b16 {%0,%1,%2,%3}, [%4];"
        : "=r"(r[0]), "=r"(r[1]), "=r"(r[2]), "=r"(r[3]) : "r"(a));
}
__device__ __forceinline__ void ldsm4t(uint32_t* r, uint32_t a) {
    asm volatile("ldmatrix.sync.aligned.m8n8.x4.trans.shared.b16 {%0,%1,%2,%3}, [%4];"
        : "=r"(r[0]), "=r"(r[1]), "=r"(r[2]), "=r"(r[3]) : "r"(a));
}
__device__ __forceinline__ void mma_bf16(float* c, const uint32_t* a, uint32_t b0, uint32_t b1) {
    asm volatile("mma.sync.aligned.m16n8k16.row.col.f32.bf16.bf16.f32 "
        "{%0,%1,%2,%3}, {%4,%5,%6,%7}, {%8,%9}, {%0,%1,%2,%3};"
        : "+f"(c[0]), "+f"(c[1]), "+f"(c[2]), "+f"(c[3])
        : "r"(a[0]), "r"(a[1]), "r"(a[2]), "r"(a[3]), "r"(b0), "r"(b1));
}
__device__ __forceinline__ void cpasync16(uint32_t s, const void* g) {
    asm volatile("cp.async.cg.shared.global [%0], [%1], 16;" :: "r"(s), "l"(g));
}
__device__ __forceinline__ void cpasync4(uint32_t s, const void* g) {
    asm volatile("cp.async.ca.shared.global [%0], [%1], 4;" :: "r"(s), "l"(g));
}
__device__ __forceinline__ uint32_t packbf2(float lo, float hi) {
    __nv_bfloat162 h = __floats2bfloat162_rn(lo, hi);
    return *(uint32_t*)&h;
}

// ============================================================
// K0: copy former+latter into out channels [0,512). Shift region
//     [512,768) is written densely by k_reduce (zeros + attn).
// ============================================================
__global__ void k_copy(const float4* __restrict__ x4, float4* __restrict__ o4) {
    int i = blockIdx.x * 256 + threadIdx.x;           // < 4194304
    int b = i >> 19;                                  // / (512*4096/4)
    int r = i & 524287;
    o4[(size_t)b * (OUTC * N / 4) + r] = x4[i];
}

// ============================================================
// K1: inv-norm of latter per (b, n)
// ============================================================
__global__ void k_invnorm(const float* __restrict__ x) {
    int b = blockIdx.y;
    int n = blockIdx.x * 128 + threadIdx.x;
    const float* p = x + ((size_t)b * C + D) * N + n;
    float s = 0.f;
#pragma unroll 8
    for (int d = 0; d < D; ++d) {
        float v = p[(size_t)d * N];
        s = fmaf(v, v, s);
    }
    g_invnorm[b * N + n] = 1.0f / (sqrtf(s) + 1e-8f);
}

// ============================================================
// K2: build compact index lists + pixel->rank table
// ============================================================
__global__ void k_build_lists(const unsigned char* __restrict__ mask8) {
    __shared__ int cK[256], cH[256];
    __shared__ int byteEvidence;
    const int t = threadIdx.x;
    if (t == 0) byteEvidence = 0;
    __syncthreads();

    const unsigned int* m32 = (const unsigned int*)mask8;
    int bad = 0;
    for (int w = t; w < 1024; w += 256) {
        unsigned int v = m32[w];
        if (v != 0u && v != 1u && v != 0x3F800000u) bad = 1;
    }
    if (bad) byteEvidence = 1;
    __syncthreads();
    const bool byteMode = (byteEvidence != 0);

    const int base = t * 16;
    int ck = 0, ch = 0;
#pragma unroll
    for (int e = 0; e < 16; ++e) {
        int m = base + e;
        bool f = byteMode ? (mask8[m] != 0) : (m32[m] != 0u);
        if (f) ch++; else ck++;
    }
    cK[t] = ck; cH[t] = ch;
    __syncthreads();
    for (int off = 1; off < 256; off <<= 1) {
        int a = (t >= off) ? cK[t - off] : 0;
        int b2 = (t >= off) ? cH[t - off] : 0;
        __syncthreads();
        cK[t] += a; cH[t] += b2;
        __syncthreads();
    }
    int kb = cK[t] - ck;
    int hb = cH[t] - ch;
#pragma unroll
    for (int e = 0; e < 16; ++e) {
        int m = base + e;
        bool f = byteMode ? (mask8[m] != 0) : (m32[m] != 0u);
        if (f) { g_rank[m] = hb; g_qidx[hb++] = m; }
        else   { g_rank[m] = -1; g_kidx[kb++] = m; }
    }
    if (t == 255) { g_counts[0] = cK[255]; g_counts[1] = cH[255]; }
}

// ============================================================
// K3: pack gathered operands to bf16 row-major [row][256].
//   which: 0=K(norm latter), 1=V(former), 2=Q(norm latter @qidx)
//   Gather via cp.async.ca 4B (LDGSTS -> deep MLP, verified R10).
// ============================================================
#define PACK_SMEM (256 * 65 * 4)   // 66560 B

__global__ void k_pack(const float* __restrict__ x) {
    extern __shared__ float ts[];            // [256][65]
    __shared__ int   sIdx[64];
    __shared__ float sSc[64];
    const int b = blockIdx.y, which = blockIdx.z;
    const int row0 = blockIdx.x * 64;
    const int t = threadIdx.x;

    const int cnt = (which == 2) ? g_counts[1] : g_counts[0];
    if (row0 >= ((cnt + 63) & ~63)) return;

    const int* list = (which == 2) ? g_qidx : g_kidx;
    const float* src = (which == 1) ? (x + (size_t)b * C * N)
                                    : (x + ((size_t)b * C + D) * N);
    __nv_bfloat16* dst = (which == 0 ? g_K : (which == 1 ? g_V : g_Q))
                         + ((size_t)b * 4096 + row0) * 256;

    if (t < 64) {
        int r = row0 + t;
        int m = (r < cnt) ? list[r] : -1;
        sIdx[t] = (m >= 0) ? m : 0;
        sSc[t] = (m >= 0) ? ((which == 1) ? 1.f : g_invnorm[b * N + m]) : 0.f;
    }
    __syncthreads();

    const uint32_t tsb = smaddr(ts);
#pragma unroll 16
    for (int j = 0; j < 64; ++j) {
        int idx = t + 256 * j;
        int row = idx & 63, dd = idx >> 6;
        cpasync4(tsb + (uint32_t)((dd * 65 + row) << 2),
                 src + (size_t)dd * N + sIdx[row]);
    }
    asm volatile("cp.async.commit_group;");
    asm volatile("cp.async.wait_group 0;" ::: "memory");
    __syncthreads();

#pragma unroll 16
    for (int j = 0; j < 64; ++j) {
        dst[(size_t)j * 256 + t] = __float2bfloat16(ts[t * 65 + j] * sSc[j]);
    }
}

// ============================================================
// K4: mma flash attention, register-P, SPLIT-K over key tiles.
//   CTA = 64 hole queries x 1 batch x 1 split. 4 warps, 128 thr.
//   BK=32, double-buffered K/V. smem ~97KB -> 2 CTAs/SM
//   (__launch_bounds__(128,2)) => 2 warps/SMSP latency hiding.
//   Epilogue: smem-transpose O -> coalesced store of partials
//   g_pO[split][b][d][q] + rowsums g_pL. No writes to out here.
// ============================================================
#define SQ_   0          // 32 KB (64 rows x 256 bf16)
#define SK0_  32768      // 16 KB (32 rows)
#define SK1_  49152
#define SV0_  65536
#define SV1_  81920
#define SQN_  98304      // 64 ints
#define ATTN_SMEM 98816  // x2 = 197632 <= 228KB/SM

__device__ __forceinline__ uint32_t sw_addr(int row, int dd) {  // dd multiple of 8
    return (uint32_t)((row * 32 + ((dd >> 3) ^ (row & 7))) << 4);
}

__global__ __launch_bounds__(128, 2)
void k_attn() {
    extern __shared__ char smc[];
    const uint32_t sb = smaddr(smc);
    const int t = threadIdx.x;
    const int lane = t & 31, w = t >> 5;       // w in 0..3
    const int b = blockIdx.y, qt = blockIdx.x, split = blockIdx.z;

    const int nKnown = g_counts[0];
    const int nHole  = g_counts[1];
    const int q0 = qt * 64;
    if (q0 >= nHole) return;
    const int nQ = min(64, nHole - q0);

    const int nkt = (nKnown + 31) >> 5;        // BK=32 tiles
    const int h   = (nkt + 1) >> 1;
    const int kt0 = split ? h : 0;
    const int ktE = split ? nkt : h;
    const int L   = ktE - kt0;

    int* sQn = (int*)(smc + SQN_);
    if (t < 64) sQn[t] = (t < nQ) ? g_qidx[q0 + t] : -1;

    const __nv_bfloat16* gq = g_Q + ((size_t)b * 4096 + q0) * 256;
    const __nv_bfloat16* gk = g_K + (size_t)b * 4096 * 256;
    const __nv_bfloat16* gv = g_V + (size_t)b * 4096 * 256;

    // ---- prologue: Q; K/V tiles kt0, kt0+1 ----
#pragma unroll 4
    for (int i = t; i < 2048; i += 128) {   // Q: 64 rows x 32 chunks
        int row = i >> 5, ch = i & 31;
        cpasync16(sb + SQ_ + sw_addr(row, ch << 3), gq + row * 256 + ch * 8);
    }
#define LOAD_KV(kt_, kb_, vb_) do { \
    for (int i = t; i < 1024; i += 128) { \
        int row = i >> 5, ch = i & 31; \
        uint32_t so = sw_addr(row, ch << 3); \
        cpasync16((kb_) + so, gk + (size_t)((kt_) * 32 + row) * 256 + ch * 8); \
        cpasync16((vb_) + so, gv + (size_t)((kt_) * 32 + row) * 256 + ch * 8); \
    } \
} while (0)

    if (L > 0) { LOAD_KV(kt0, sb + SK0_, sb + SV0_); asm volatile("cp.async.commit_group;"); }
    if (L > 1) { LOAD_KV(kt0 + 1, sb + SK1_, sb + SV1_); asm volatile("cp.async.commit_group;"); }

    float O[32][4];
#pragma unroll
    for (int i = 0; i < 32; ++i) { O[i][0] = O[i][1] = O[i][2] = O[i][3] = 0.f; }
    float rs0 = 0.f, rs1 = 0.f;

    const int band = w * 16;
    const int r15 = lane & 15, chalf = lane >> 4;   // A-frag mapping
    const int l8 = lane & 7, sel = lane >> 3;       // B-frag mapping

    for (int i = 0; i < L; ++i) {
        const int kt = kt0 + i;
        if (i + 1 < L) asm volatile("cp.async.wait_group 1;" ::: "memory");
        else           asm volatile("cp.async.wait_group 0;" ::: "memory");
        __syncthreads();
        const uint32_t smk = sb + ((i & 1) ? SK1_ : SK0_);
        const uint32_t smv = sb + ((i & 1) ? SV1_ : SV0_);

        // ---- S = Q K^T : 16q x 32k ----
        float s[4][4];
#pragma unroll
        for (int j = 0; j < 4; ++j) { s[j][0] = s[j][1] = s[j][2] = s[j][3] = 0.f; }
#pragma unroll
        for (int ds = 0; ds < 16; ++ds) {
            uint32_t a[4];
            ldsm4(a, sb + SQ_ + sw_addr(band + r15, ds * 16 + chalf * 8));
#pragma unroll
            for (int g = 0; g < 2; ++g) {
                uint32_t bb[4];
                ldsm4(bb, smk + sw_addr(g * 16 + (sel >> 1) * 8 + l8, ds * 16 + (sel & 1) * 8));
                mma_bf16(s[2 * g],     a, bb[0], bb[1]);
                mma_bf16(s[2 * g + 1], a, bb[2], bb[3]);
            }
        }

        // ---- P = exp(S-1), mask pad keys, repack C-frags -> A-frags ----
        uint32_t pa[2][4];
        const int kg = kt * 32 + (lane & 3) * 2;
#pragma unroll
        for (int j = 0; j < 4; ++j) {
            float p0 = __expf(s[j][0] - 1.f), p1 = __expf(s[j][1] - 1.f);
            float p2 = __expf(s[j][2] - 1.f), p3 = __expf(s[j][3] - 1.f);
            int keyg = kg + j * 8;
            if (keyg >= nKnown)     { p0 = 0.f; p2 = 0.f; }
            if (keyg + 1 >= nKnown) { p1 = 0.f; p3 = 0.f; }
            rs0 += p0 + p1;
            rs1 += p2 + p3;
            pa[j >> 1][(j & 1) * 2]     = packbf2(p0, p1);
            pa[j >> 1][(j & 1) * 2 + 1] = packbf2(p2, p3);
        }

        // ---- O += P V : 16q x 256d ----
#pragma unroll
        for (int ks = 0; ks < 2; ++ks) {
#pragma unroll
            for (int np = 0; np < 16; ++np) {
                uint32_t v[4];
                ldsm4t(v, smv + sw_addr(ks * 16 + (sel & 1) * 8 + l8, np * 16 + (sel >> 1) * 8));
                mma_bf16(O[2 * np],     pa[ks], v[0], v[1]);
                mma_bf16(O[2 * np + 1], pa[ks], v[2], v[3]);
            }
        }

        __syncthreads();   // all warps done reading buffer i&1
        if (i + 2 < L) {
            const uint32_t kb_ = sb + ((i & 1) ? SK1_ : SK0_);
            const uint32_t vb_ = sb + ((i & 1) ? SV1_ : SV0_);
            LOAD_KV(kt + 2, kb_, vb_);
            asm volatile("cp.async.commit_group;");
        }
    }

    // ---- rowsum quad-reduce, write partial L ----
    rs0 += __shfl_xor_sync(0xffffffffu, rs0, 1);
    rs0 += __shfl_xor_sync(0xffffffffu, rs0, 2);
    rs1 += __shfl_xor_sync(0xffffffffu, rs1, 1);
    rs1 += __shfl_xor_sync(0xffffffffu, rs1, 2);
    const int qr0 = band + (lane >> 2), qr1 = qr0 + 8;
    if ((lane & 3) == 0) {
        g_pL[(split * B + b) * 4096 + q0 + qr0] = rs0;
        g_pL[(split * B + b) * 4096 + q0 + qr1] = rs1;
    }

    // ---- transpose O via smem (reuse), coalesced partial store ----
    float* tsO = (float*)smc;    // [256][65] = 66560 B, fits in 98816
#pragma unroll
    for (int nt = 0; nt < 32; ++nt) {
        int d0 = nt * 8 + (lane & 3) * 2;
        tsO[d0 * 65 + qr0]       = O[nt][0];
        tsO[(d0 + 1) * 65 + qr0] = O[nt][1];
        tsO[d0 * 65 + qr1]       = O[nt][2];
        tsO[(d0 + 1) * 65 + qr1] = O[nt][3];
    }
    __syncthreads();
    float* po = g_pO + ((size_t)(split * B + b) * 256) * 4096 + q0;
#pragma unroll 8
    for (int j = 0; j < 128; ++j) {
        int idx = t + 128 * j;
        int q = idx & 63, d = idx >> 6;
        po[(size_t)d * 4096 + q] = tsO[d * 65 + q];
    }
}

// ============================================================
// K5: reduce splits + write the ENTIRE shift channel region
//     (zeros at known pixels, normalized attn at holes).
//     out[b][512+d][n], fully coalesced.
// ============================================================
__global__ void k_reduce(float* __restrict__ out) {
    const int n = blockIdx.x * 256 + threadIdx.x;
    const int d = blockIdx.y;
    const int b = blockIdx.z;
    const int r = g_rank[n];
    float v = 0.f;
    if (r >= 0) {
        float l = g_pL[b * 4096 + r] + g_pL[(B + b) * 4096 + r];
        float o0 = g_pO[((size_t)b * 256 + d) * 4096 + r];
        float o1 = g_pO[((size_t)(B + b) * 256 + d) * 4096 + r];
        v = (o0 + o1) / l;
    }
    out[((size_t)b * OUTC + 2 * D + d) * N + n] = v;
}

// ============================================================
extern "C" void kernel_launch(void* const* d_in, const int* in_sizes, int n_in,
                              void* d_out, int out_size) {
    const float* x = (const float*)d_in[0];
    const unsigned char* mask = (const unsigned char*)d_in[1];
    float* out = (float*)d_out;
    (void)in_sizes; (void)n_in; (void)out_size;

    k_copy<<<(B * C * N / 4) / 256, 256>>>((const float4*)x, (float4*)out);
    k_invnorm<<<dim3(N / 128, B), 128>>>(x);
    k_build_lists<<<1, 256>>>(mask);

    cudaFuncSetAttribute(k_pack, cudaFuncAttributeMaxDynamicSharedMemorySize, PACK_SMEM);
    k_pack<<<dim3(64, B, 3), 256, PACK_SMEM>>>(x);

    cudaFuncSetAttribute(k_attn, cudaFuncAttributeMaxDynamicSharedMemorySize, ATTN_SMEM);
    // 64 q-tiles x 8 batches x 2 key-splits; inactive tiles early-exit
    k_attn<<<dim3(64, B, 2), 128, ATTN_SMEM>>>();

    k_reduce<<<dim3(N / 256, D, B), 256>>>(out);
}